// round 14
// baseline (speedup 1.0000x reference)
#include <cuda_runtime.h>
#include <cuda_fp16.h>

#define NMAX 100000
#define EMAX 1600000
#define EPAD (EMAX + 8 * NMAX)
#define HDIM 64
#define HC 32
#define NLAYERS 3
#define BN_EPS 1e-5f
#define SCAN_BLK 1024
#define SCAN_MAXB 128

// ---- scratch (device globals; no allocation allowed) ----
__device__ __half2 g_hs2[(NMAX + 1) * 32]; // (h @ W) * dinv[row]; row n = zero sentinel
__device__ float g_agg[NMAX * HDIM];       // pre-BN aggregated features (fp32)
__device__ int   g_cnt [NMAX];             // in-degree counts (left at 0 on exit)
__device__ float g_dinv[NMAX];             // (deg+1)^-1/2
__device__ int   g_row [NMAX + 1];         // padded CSR row pointers (by dst)
__device__ int   g_rank[EMAX];             // per-edge rank within its dst bucket
__device__ int   g_srcs[EPAD];             // src ids sorted by dst, padded to 8
__device__ volatile int g_part[SCAN_MAXB]; // lookback partials (total+1)
__device__ float g_stats[NLAYERS][2 * HDIM]; // per-layer channel sum, sumsq
__device__ __half g_w16[NLAYERS][HDIM * HDIM]; // conv weights pre-converted fp16

static __device__ __forceinline__ unsigned s2u(const void* p) {
    return (unsigned)__cvta_generic_to_shared(p);
}

// ---------------------------------------------------------------------------
// count in-degrees, record per-edge rank; block 0 zeroes partials + BN stats;
// blocks 1..NLAYERS convert conv_W[layer] to fp16; block NLAYERS+1 zeroes the
// sentinel hs2 row (row n).
__global__ void k_count_deg(const int* __restrict__ dst, int e, int n,
                            const float* __restrict__ conv_W) {
    int i = blockIdx.x * blockDim.x + threadIdx.x;
    if (blockIdx.x == 0) {
        if (threadIdx.x < SCAN_MAXB) *(int*)&g_part[threadIdx.x] = 0;
        for (int j = threadIdx.x; j < NLAYERS * 2 * HDIM; j += 256)
            (&g_stats[0][0])[j] = 0.0f;
    } else if (blockIdx.x <= NLAYERS) {
        int l = blockIdx.x - 1;
        const float* W = conv_W + l * HDIM * HDIM;
        for (int j = threadIdx.x; j < HDIM * HDIM / 4; j += 256) {
            float4 w = *reinterpret_cast<const float4*>(&W[j * 4]);
            __half2 h0 = __floats2half2_rn(w.x, w.y);
            __half2 h1 = __floats2half2_rn(w.z, w.w);
            uint2 pk;
            pk.x = *reinterpret_cast<unsigned*>(&h0);
            pk.y = *reinterpret_cast<unsigned*>(&h1);
            *reinterpret_cast<uint2*>(&g_w16[l][j * 4]) = pk;
        }
    } else if (blockIdx.x == NLAYERS + 1) {
        if (threadIdx.x < 32)
            g_hs2[n * 32 + threadIdx.x] = __floats2half2_rn(0.f, 0.f);
    }
    if (i < e) g_rank[i] = atomicAdd(&g_cnt[dst[i]], 1);
}

// fused scan: dinv from real counts + exclusive prefix of PADDED counts
__global__ void k_scan_fused(int n) {
    __shared__ int sh[256];
    int tid = threadIdx.x, b = blockIdx.x;
    int base = b * SCAN_BLK + tid * 4;

    int v[4]; int mine = 0;
    if (base + 4 <= n) {
        int4 c = *reinterpret_cast<const int4*>(&g_cnt[base]);
        g_dinv[base + 0] = rsqrtf((float)c.x + 1.0f);
        g_dinv[base + 1] = rsqrtf((float)c.y + 1.0f);
        g_dinv[base + 2] = rsqrtf((float)c.z + 1.0f);
        g_dinv[base + 3] = rsqrtf((float)c.w + 1.0f);
        v[0] = (c.x + 7) & ~7; v[1] = (c.y + 7) & ~7;
        v[2] = (c.z + 7) & ~7; v[3] = (c.w + 7) & ~7;
        mine = v[0] + v[1] + v[2] + v[3];
    } else {
#pragma unroll
        for (int k = 0; k < 4; k++) {
            v[k] = 0;
            if (base + k < n) {
                int c = g_cnt[base + k];
                g_dinv[base + k] = rsqrtf((float)c + 1.0f);
                v[k] = (c + 7) & ~7;
                mine += v[k];
            }
        }
    }

    sh[tid] = mine;
    __syncthreads();
    for (int o = 1; o < 256; o <<= 1) {
        int t = (tid >= o) ? sh[tid - o] : 0;
        __syncthreads();
        sh[tid] += t;
        __syncthreads();
    }
    int excl = sh[tid] - mine;
    int total = sh[255];

    if (tid == 0) atomicExch((int*)&g_part[b], total + 1);
    int pref = 0;
    for (int i = tid; i < b; i += 256) {
        int p;
        while ((p = g_part[i]) == 0) {}
        pref += p - 1;
    }
    __syncthreads();
    sh[tid] = pref;
    __syncthreads();
    for (int o = 128; o > 0; o >>= 1) {
        if (tid < o) sh[tid] += sh[tid + o];
        __syncthreads();
    }
    int off = sh[0] + excl;

#pragma unroll
    for (int k = 0; k < 4; k++) {
        int idx = base + k;
        if (idx < n) {
            g_row[idx] = off;
            off += v[k];
            if (idx == n - 1) g_row[n] = off;
        }
    }
}

// ---------------------------------------------------------------------------
// FUSED: blocks [0, gemm_blocks) run GEMM layer 0 (input-proj prologue);
// blocks [gemm_blocks, ...) run bucket placement + pad fill + g_cnt re-zero.
// Both depend only on k_scan_fused; aggregate-0 depends on both.
#define GROWS 128
#define ASTRIDE 72   // halves; 144B rows: 16B aligned, ldmatrix conflict-free
__global__ void __launch_bounds__(256) k_bucket_gemm0(
    const int* __restrict__ ei, int e, int n, int gemm_blocks,
    const float* __restrict__ x, const float* __restrict__ Win,
    const float* __restrict__ bin) {
    __shared__ __half Asm[GROWS * ASTRIDE];
    __shared__ __half Wsm[HDIM * ASTRIDE];

    int tid = threadIdx.x;

    if (blockIdx.x >= gemm_blocks) {
        // ---- bucket body ----
        int i = (blockIdx.x - gemm_blocks) * 256 + tid;
        if (i < n) {
            int c = g_cnt[i];
            int pc = (c + 7) & ~7;
            int base = g_row[i];
            for (int k = c; k < pc; k++) g_srcs[base + k] = n;
            g_cnt[i] = 0;
        }
        if (i < e) {
            int s = ei[i];
            int d = ei[e + i];
            g_srcs[g_row[d] + g_rank[i]] = s;
        }
        return;
    }

    // ---- GEMM layer-0 body (input projection prologue) ----
    int node0 = blockIdx.x * GROWS;

    for (int i = tid; i < HDIM * HDIM / 8; i += 256) {
        uint4 w = *reinterpret_cast<const uint4*>(&g_w16[0][i * 8]);
        int r = i >> 3;
        int c = (i * 8) & 63;
        *reinterpret_cast<uint4*>(&Wsm[r * ASTRIDE + c]) = w;
    }

#pragma unroll
    for (int it = 0; it < 8; it++) {
        int idx = tid + it * 256;
        int row = idx >> 4;
        int c4 = (idx & 15) * 4;
        int node = node0 + row;
        float4 v = make_float4(0.f, 0.f, 0.f, 0.f);
        if (node < n) {
            v = *reinterpret_cast<const float4*>(&bin[c4]);
#pragma unroll
            for (int k = 0; k < 5; k++) {
                float xv = __ldg(&x[node * 5 + k]);
                float4 w = *reinterpret_cast<const float4*>(&Win[k * HDIM + c4]);
                v.x = fmaf(xv, w.x, v.x);
                v.y = fmaf(xv, w.y, v.y);
                v.z = fmaf(xv, w.z, v.z);
                v.w = fmaf(xv, w.w, v.w);
            }
            v.x = fmaxf(v.x, 0.f); v.y = fmaxf(v.y, 0.f);
            v.z = fmaxf(v.z, 0.f); v.w = fmaxf(v.w, 0.f);
        }
        __half2 h0 = __floats2half2_rn(v.x, v.y);
        __half2 h1 = __floats2half2_rn(v.z, v.w);
        uint2 pk;
        pk.x = *reinterpret_cast<unsigned*>(&h0);
        pk.y = *reinterpret_cast<unsigned*>(&h1);
        *reinterpret_cast<uint2*>(&Asm[row * ASTRIDE + c4]) = pk;
    }
    __syncthreads();

    int warp = tid >> 5, lane = tid & 31;
    int wrow = warp * 16;

    unsigned a[4][4];
    {
        int r = lane & 15;
        int cb = (lane >> 4) << 3;
#pragma unroll
        for (int ks = 0; ks < 4; ks++) {
            unsigned addr = s2u(&Asm[(wrow + r) * ASTRIDE + ks * 16 + cb]);
            asm volatile("ldmatrix.sync.aligned.m8n8.x4.shared.b16 {%0,%1,%2,%3}, [%4];"
                         : "=r"(a[ks][0]), "=r"(a[ks][1]), "=r"(a[ks][2]), "=r"(a[ks][3])
                         : "r"(addr));
        }
    }

    float acc[8][4];
#pragma unroll
    for (int nt = 0; nt < 8; nt++)
#pragma unroll
        for (int q = 0; q < 4; q++) acc[nt][q] = 0.0f;

#pragma unroll
    for (int nt = 0; nt < 8; nt++) {
#pragma unroll
        for (int ks = 0; ks < 4; ks++) {
            unsigned b0, b1;
            int r = lane & 15;
            unsigned baddr = s2u(&Wsm[(ks * 16 + r) * ASTRIDE + nt * 8]);
            asm volatile("ldmatrix.sync.aligned.m8n8.x2.trans.shared.b16 {%0,%1}, [%2];"
                         : "=r"(b0), "=r"(b1) : "r"(baddr));
            asm volatile(
                "mma.sync.aligned.m16n8k16.row.col.f32.f16.f16.f32 "
                "{%0,%1,%2,%3}, {%4,%5,%6,%7}, {%8,%9}, {%0,%1,%2,%3};"
                : "+f"(acc[nt][0]), "+f"(acc[nt][1]), "+f"(acc[nt][2]), "+f"(acc[nt][3])
                : "r"(a[ks][0]), "r"(a[ks][1]), "r"(a[ks][2]), "r"(a[ks][3]),
                  "r"(b0), "r"(b1));
        }
    }

    int gr = lane >> 2;
    int qp = lane & 3;
    int node_a = node0 + wrow + gr;
    int node_b = node_a + 8;
    float dia = (node_a < n) ? g_dinv[node_a] : 0.f;
    float dib = (node_b < n) ? g_dinv[node_b] : 0.f;
#pragma unroll
    for (int nt = 0; nt < 8; nt++) {
        if (node_a < n)
            g_hs2[node_a * 32 + nt * 4 + qp] =
                __floats2half2_rn(acc[nt][0] * dia, acc[nt][1] * dia);
        if (node_b < n)
            g_hs2[node_b * 32 + nt * 4 + qp] =
                __floats2half2_rn(acc[nt][2] * dib, acc[nt][3] * dib);
    }
}

// ---------------------------------------------------------------------------
// Tensor-core GEMM (exact R10/R11 structure) for layers 1,2 (BN prologue).
__global__ void __launch_bounds__(256) k_gemm_mma(
    int n, int layer,
    const float* __restrict__ gamma, const float* __restrict__ beta) {
    __shared__ __half Asm[GROWS * ASTRIDE];
    __shared__ __half Wsm[HDIM * ASTRIDE];
    __shared__ float s_sc[HDIM], s_sf[HDIM];

    int tid = threadIdx.x;
    int node0 = blockIdx.x * GROWS;

    if (tid < HDIM) {
        float inv_n = 1.0f / (float)n;
        float mean = g_stats[layer - 1][tid] * inv_n;
        float var = g_stats[layer - 1][HDIM + tid] * inv_n - mean * mean;
        float inv = rsqrtf(var + BN_EPS);
        float sc = gamma[tid] * inv;
        s_sc[tid] = sc;
        s_sf[tid] = beta[tid] - mean * sc;
    }
    __syncthreads();

    for (int i = tid; i < HDIM * HDIM / 8; i += 256) {
        uint4 w = *reinterpret_cast<const uint4*>(&g_w16[layer][i * 8]);
        int r = i >> 3;
        int c = (i * 8) & 63;
        *reinterpret_cast<uint4*>(&Wsm[r * ASTRIDE + c]) = w;
    }

#pragma unroll
    for (int it = 0; it < 8; it++) {
        int idx = tid + it * 256;
        int row = idx >> 4;
        int c4 = (idx & 15) * 4;
        int node = node0 + row;
        float4 v = make_float4(0.f, 0.f, 0.f, 0.f);
        if (node < n) {
            v = *reinterpret_cast<const float4*>(&g_agg[node * HDIM + c4]);
            v.x = fmaf(v.x, s_sc[c4 + 0], s_sf[c4 + 0]);
            v.y = fmaf(v.y, s_sc[c4 + 1], s_sf[c4 + 1]);
            v.z = fmaf(v.z, s_sc[c4 + 2], s_sf[c4 + 2]);
            v.w = fmaf(v.w, s_sc[c4 + 3], s_sf[c4 + 3]);
            v.x = fmaxf(v.x, 0.f); v.y = fmaxf(v.y, 0.f);
            v.z = fmaxf(v.z, 0.f); v.w = fmaxf(v.w, 0.f);
        }
        __half2 h0 = __floats2half2_rn(v.x, v.y);
        __half2 h1 = __floats2half2_rn(v.z, v.w);
        uint2 pk;
        pk.x = *reinterpret_cast<unsigned*>(&h0);
        pk.y = *reinterpret_cast<unsigned*>(&h1);
        *reinterpret_cast<uint2*>(&Asm[row * ASTRIDE + c4]) = pk;
    }
    __syncthreads();

    int warp = tid >> 5, lane = tid & 31;
    int wrow = warp * 16;

    unsigned a[4][4];
    {
        int r = lane & 15;
        int cb = (lane >> 4) << 3;
#pragma unroll
        for (int ks = 0; ks < 4; ks++) {
            unsigned addr = s2u(&Asm[(wrow + r) * ASTRIDE + ks * 16 + cb]);
            asm volatile("ldmatrix.sync.aligned.m8n8.x4.shared.b16 {%0,%1,%2,%3}, [%4];"
                         : "=r"(a[ks][0]), "=r"(a[ks][1]), "=r"(a[ks][2]), "=r"(a[ks][3])
                         : "r"(addr));
        }
    }

    float acc[8][4];
#pragma unroll
    for (int nt = 0; nt < 8; nt++)
#pragma unroll
        for (int q = 0; q < 4; q++) acc[nt][q] = 0.0f;

#pragma unroll
    for (int nt = 0; nt < 8; nt++) {
#pragma unroll
        for (int ks = 0; ks < 4; ks++) {
            unsigned b0, b1;
            int r = lane & 15;
            unsigned baddr = s2u(&Wsm[(ks * 16 + r) * ASTRIDE + nt * 8]);
            asm volatile("ldmatrix.sync.aligned.m8n8.x2.trans.shared.b16 {%0,%1}, [%2];"
                         : "=r"(b0), "=r"(b1) : "r"(baddr));
            asm volatile(
                "mma.sync.aligned.m16n8k16.row.col.f32.f16.f16.f32 "
                "{%0,%1,%2,%3}, {%4,%5,%6,%7}, {%8,%9}, {%0,%1,%2,%3};"
                : "+f"(acc[nt][0]), "+f"(acc[nt][1]), "+f"(acc[nt][2]), "+f"(acc[nt][3])
                : "r"(a[ks][0]), "r"(a[ks][1]), "r"(a[ks][2]), "r"(a[ks][3]),
                  "r"(b0), "r"(b1));
        }
    }

    int gr = lane >> 2;
    int qp = lane & 3;
    int node_a = node0 + wrow + gr;
    int node_b = node_a + 8;
    float dia = (node_a < n) ? g_dinv[node_a] : 0.f;
    float dib = (node_b < n) ? g_dinv[node_b] : 0.f;
#pragma unroll
    for (int nt = 0; nt < 8; nt++) {
        if (node_a < n)
            g_hs2[node_a * 32 + nt * 4 + qp] =
                __floats2half2_rn(acc[nt][0] * dia, acc[nt][1] * dia);
        if (node_b < n)
            g_hs2[node_b * 32 + nt * 4 + qp] =
                __floats2half2_rn(acc[nt][2] * dib, acc[nt][3] * dib);
    }
}

// ---------------------------------------------------------------------------
// pull-based aggregation + BN stats. Padded buckets (sentinel n, zero row).
// NODES_PER_WARP=2: 6250 blocks for finer wave balance.
#define AGG_WARPS 8
#define NODES_PER_WARP 2
__global__ void k_aggregate(int n, int layer) {
    __shared__ float s_sum[HDIM], s_sq[HDIM];
    int tid = threadIdx.x, lane = tid & 31, warp = tid >> 5;
    if (tid < HDIM) { s_sum[tid] = 0.f; s_sq[tid] = 0.f; }
    __syncthreads();

    float ls0 = 0.f, lq0 = 0.f, ls1 = 0.f, lq1 = 0.f;
    int node0 = (blockIdx.x * AGG_WARPS + warp) * NODES_PER_WARP;

    for (int i = 0; i < NODES_PER_WARP; i++) {
        int node = node0 + i;
        if (node >= n) break;
        int beg = g_row[node], end = g_row[node + 1];
        float a0 = 0.f, a1 = 0.f;
        for (int j = beg; j < end; j += 8) {
            int4 sa = *reinterpret_cast<const int4*>(&g_srcs[j]);
            int4 sb = *reinterpret_cast<const int4*>(&g_srcs[j + 4]);
            float2 f[8];
            f[0] = __half22float2(g_hs2[sa.x * 32 + lane]);
            f[1] = __half22float2(g_hs2[sa.y * 32 + lane]);
            f[2] = __half22float2(g_hs2[sa.z * 32 + lane]);
            f[3] = __half22float2(g_hs2[sa.w * 32 + lane]);
            f[4] = __half22float2(g_hs2[sb.x * 32 + lane]);
            f[5] = __half22float2(g_hs2[sb.y * 32 + lane]);
            f[6] = __half22float2(g_hs2[sb.z * 32 + lane]);
            f[7] = __half22float2(g_hs2[sb.w * 32 + lane]);
#pragma unroll
            for (int u = 0; u < 8; u++) { a0 += f[u].x; a1 += f[u].y; }
        }
        float2 self = __half22float2(g_hs2[node * 32 + lane]);
        float di = g_dinv[node];
        a0 = (a0 + self.x) * di;
        a1 = (a1 + self.y) * di;
        float2 o; o.x = a0; o.y = a1;
        *reinterpret_cast<float2*>(&g_agg[node * HDIM + 2 * lane]) = o;
        ls0 += a0; lq0 = fmaf(a0, a0, lq0);
        ls1 += a1; lq1 = fmaf(a1, a1, lq1);
    }

    atomicAdd(&s_sum[2 * lane], ls0);
    atomicAdd(&s_sq[2 * lane], lq0);
    atomicAdd(&s_sum[2 * lane + 1], ls1);
    atomicAdd(&s_sq[2 * lane + 1], lq1);
    __syncthreads();
    if (tid < HDIM) {
        atomicAdd(&g_stats[layer][tid], s_sum[tid]);
        atomicAdd(&g_stats[layer][HDIM + tid], s_sq[tid]);
    }
}

// ---------------------------------------------------------------------------
// classifier with in-block final BN+ReLU: out = relu(bn(agg) @ W1 + b1) @ W2 + b2
__global__ void k_classifier(const float* __restrict__ W1,
                             const float* __restrict__ b1,
                             const float* __restrict__ W2,
                             const float* __restrict__ b2,
                             const float* __restrict__ gamma,
                             const float* __restrict__ beta,
                             float* __restrict__ out, int n) {
    __shared__ float W1sm[HDIM * HC];
    __shared__ float s_sc[HDIM], s_sf[HDIM];
    int tid = threadIdx.x;
    if (tid < HDIM) {
        float inv_n = 1.0f / (float)n;
        float mean = g_stats[NLAYERS - 1][tid] * inv_n;
        float var = g_stats[NLAYERS - 1][HDIM + tid] * inv_n - mean * mean;
        float inv = rsqrtf(var + BN_EPS);
        float sc = gamma[tid] * inv;
        s_sc[tid] = sc;
        s_sf[tid] = beta[tid] - mean * sc;
    }
#pragma unroll
    for (int i = tid; i < HDIM * HC; i += 256) W1sm[i] = W1[i];
    __syncthreads();

    int lane = tid & 31;
    int warp = tid >> 5;
    float b1v = b1[lane];
    float w2v = W2[lane];
    float b2v = b2[0];
    float sc0 = s_sc[lane],      sf0 = s_sf[lane];
    float sc1 = s_sc[lane + 32], sf1 = s_sf[lane + 32];
    int base = blockIdx.x * 64 + warp * 8;

    for (int i = 0; i < 8; i++) {
        int node = base + i;
        if (node >= n) break;
        float h0 = fmaxf(fmaf(g_agg[node * HDIM + lane],      sc0, sf0), 0.f);
        float h1 = fmaxf(fmaf(g_agg[node * HDIM + 32 + lane], sc1, sf1), 0.f);
        float acc = b1v;
#pragma unroll
        for (int k = 0; k < 32; k++)
            acc = fmaf(__shfl_sync(0xFFFFFFFFu, h0, k), W1sm[k * HC + lane], acc);
#pragma unroll
        for (int k = 0; k < 32; k++)
            acc = fmaf(__shfl_sync(0xFFFFFFFFu, h1, k), W1sm[(k + 32) * HC + lane], acc);
        float r = fmaxf(acc, 0.0f) * w2v;
#pragma unroll
        for (int off = 16; off > 0; off >>= 1)
            r += __shfl_xor_sync(0xFFFFFFFFu, r, off);
        if (lane == 0) out[node] = r + b2v;
    }
}

// ---------------------------------------------------------------------------
extern "C" void kernel_launch(void* const* d_in, const int* in_sizes, int n_in,
                              void* d_out, int out_size) {
    const float* x        = (const float*)d_in[0];
    const int*   ei       = (const int*)d_in[1];
    const float* W_in     = (const float*)d_in[2];
    const float* b_in     = (const float*)d_in[3];
    const float* conv_W   = (const float*)d_in[4];
    // d_in[5] = conv_b : cancels exactly inside BatchNorm -> unused
    const float* bn_gamma = (const float*)d_in[6];
    const float* bn_beta  = (const float*)d_in[7];
    const float* W1       = (const float*)d_in[8];
    const float* b1       = (const float*)d_in[9];
    const float* W2       = (const float*)d_in[10];
    const float* b2       = (const float*)d_in[11];
    float* out = (float*)d_out;

    int n = in_sizes[0] / 5;
    int e = in_sizes[1] / 2;
    int nb = (n + SCAN_BLK - 1) / SCAN_BLK;

    int gemm_blocks = (n + GROWS - 1) / GROWS;
    int bucket_blocks = (e + 255) / 256;
    int agg_blocks = (n + AGG_WARPS * NODES_PER_WARP - 1) / (AGG_WARPS * NODES_PER_WARP);

    k_count_deg<<<bucket_blocks, 256>>>(ei + e, e, n, conv_W);
    k_scan_fused<<<nb, 256>>>(n);

    // fused: GEMM layer 0 (blocks [0,gemm_blocks)) + bucket (rest)
    k_bucket_gemm0<<<gemm_blocks + bucket_blocks, 256>>>(
        ei, e, n, gemm_blocks, x, W_in, b_in);
    k_aggregate<<<agg_blocks, 256>>>(n, 0);

    for (int l = 1; l < NLAYERS; l++) {
        k_gemm_mma<<<gemm_blocks, 256>>>(
            n, l, bn_gamma + (l - 1) * HDIM, bn_beta + (l - 1) * HDIM);
        k_aggregate<<<agg_blocks, 256>>>(n, l);
    }

    k_classifier<<<(n + 63) / 64, 256>>>(
        W1, b1, W2, b2,
        bn_gamma + (NLAYERS - 1) * HDIM, bn_beta + (NLAYERS - 1) * HDIM, out, n);
}

// round 15
// speedup vs baseline: 1.0475x; 1.0475x over previous
#include <cuda_runtime.h>
#include <cuda_fp16.h>

#define NMAX 100000
#define EMAX 1600000
#define EPAD (EMAX + 8 * NMAX)
#define HDIM 64
#define HC 32
#define NLAYERS 3
#define BN_EPS 1e-5f
#define SCAN_BLK 1024
#define SCAN_MAXB 128

// ---- scratch (device globals; no allocation allowed) ----
__device__ __half2 g_hs2[(NMAX + 1) * 32]; // (h @ W) * dinv[row]; row n = zero sentinel
__device__ float g_agg[NMAX * HDIM];       // pre-BN aggregated features (fp32)
__device__ int   g_cnt [NMAX];             // in-degree counts (left at 0 on exit)
__device__ float g_dinv[NMAX];             // (deg+1)^-1/2
__device__ int   g_row [NMAX + 1];         // padded CSR row pointers (by dst)
__device__ int   g_rank[EMAX];             // per-edge rank within its dst bucket
__device__ int   g_srcs[EPAD];             // src ids sorted by dst, padded to 8
__device__ volatile int g_part[SCAN_MAXB]; // lookback partials (total+1)
__device__ float g_stats[NLAYERS][2 * HDIM]; // per-layer channel sum, sumsq
__device__ __half g_w16[NLAYERS][HDIM * HDIM]; // conv weights pre-converted fp16

static __device__ __forceinline__ unsigned s2u(const void* p) {
    return (unsigned)__cvta_generic_to_shared(p);
}

// ---------------------------------------------------------------------------
// count in-degrees, record per-edge rank; block 0 zeroes partials + BN stats;
// blocks 1..NLAYERS convert conv_W[layer] to fp16; block NLAYERS+1 zeroes the
// sentinel hs2 row (row n).
__global__ void k_count_deg(const int* __restrict__ dst, int e, int n,
                            const float* __restrict__ conv_W) {
    int i = blockIdx.x * blockDim.x + threadIdx.x;
    if (blockIdx.x == 0) {
        if (threadIdx.x < SCAN_MAXB) *(int*)&g_part[threadIdx.x] = 0;
        for (int j = threadIdx.x; j < NLAYERS * 2 * HDIM; j += 256)
            (&g_stats[0][0])[j] = 0.0f;
    } else if (blockIdx.x <= NLAYERS) {
        int l = blockIdx.x - 1;
        const float* W = conv_W + l * HDIM * HDIM;
        for (int j = threadIdx.x; j < HDIM * HDIM / 4; j += 256) {
            float4 w = *reinterpret_cast<const float4*>(&W[j * 4]);
            __half2 h0 = __floats2half2_rn(w.x, w.y);
            __half2 h1 = __floats2half2_rn(w.z, w.w);
            uint2 pk;
            pk.x = *reinterpret_cast<unsigned*>(&h0);
            pk.y = *reinterpret_cast<unsigned*>(&h1);
            *reinterpret_cast<uint2*>(&g_w16[l][j * 4]) = pk;
        }
    } else if (blockIdx.x == NLAYERS + 1) {
        if (threadIdx.x < 32)
            g_hs2[n * 32 + threadIdx.x] = __floats2half2_rn(0.f, 0.f);
    }
    if (i < e) g_rank[i] = atomicAdd(&g_cnt[dst[i]], 1);
}

// fused scan: dinv from real counts + exclusive prefix of PADDED counts
__global__ void k_scan_fused(int n) {
    __shared__ int sh[256];
    int tid = threadIdx.x, b = blockIdx.x;
    int base = b * SCAN_BLK + tid * 4;

    int v[4]; int mine = 0;
    if (base + 4 <= n) {
        int4 c = *reinterpret_cast<const int4*>(&g_cnt[base]);
        g_dinv[base + 0] = rsqrtf((float)c.x + 1.0f);
        g_dinv[base + 1] = rsqrtf((float)c.y + 1.0f);
        g_dinv[base + 2] = rsqrtf((float)c.z + 1.0f);
        g_dinv[base + 3] = rsqrtf((float)c.w + 1.0f);
        v[0] = (c.x + 7) & ~7; v[1] = (c.y + 7) & ~7;
        v[2] = (c.z + 7) & ~7; v[3] = (c.w + 7) & ~7;
        mine = v[0] + v[1] + v[2] + v[3];
    } else {
#pragma unroll
        for (int k = 0; k < 4; k++) {
            v[k] = 0;
            if (base + k < n) {
                int c = g_cnt[base + k];
                g_dinv[base + k] = rsqrtf((float)c + 1.0f);
                v[k] = (c + 7) & ~7;
                mine += v[k];
            }
        }
    }

    sh[tid] = mine;
    __syncthreads();
    for (int o = 1; o < 256; o <<= 1) {
        int t = (tid >= o) ? sh[tid - o] : 0;
        __syncthreads();
        sh[tid] += t;
        __syncthreads();
    }
    int excl = sh[tid] - mine;
    int total = sh[255];

    if (tid == 0) atomicExch((int*)&g_part[b], total + 1);
    int pref = 0;
    for (int i = tid; i < b; i += 256) {
        int p;
        while ((p = g_part[i]) == 0) {}
        pref += p - 1;
    }
    __syncthreads();
    sh[tid] = pref;
    __syncthreads();
    for (int o = 128; o > 0; o >>= 1) {
        if (tid < o) sh[tid] += sh[tid + o];
        __syncthreads();
    }
    int off = sh[0] + excl;

#pragma unroll
    for (int k = 0; k < 4; k++) {
        int idx = base + k;
        if (idx < n) {
            g_row[idx] = off;
            off += v[k];
            if (idx == n - 1) g_row[n] = off;
        }
    }
}

// ---------------------------------------------------------------------------
// FUSED: blocks [0, gemm_blocks) run GEMM layer 0 (input-proj prologue);
// blocks [gemm_blocks, ...) run bucket placement + pad fill + g_cnt re-zero.
#define GROWS 128
#define ASTRIDE 72   // halves; 144B rows: 16B aligned, ldmatrix conflict-free
__global__ void __launch_bounds__(256) k_bucket_gemm0(
    const int* __restrict__ ei, int e, int n, int gemm_blocks,
    const float* __restrict__ x, const float* __restrict__ Win,
    const float* __restrict__ bin) {
    __shared__ __half Asm[GROWS * ASTRIDE];
    __shared__ __half Wsm[HDIM * ASTRIDE];

    int tid = threadIdx.x;

    if (blockIdx.x >= gemm_blocks) {
        // ---- bucket body ----
        int i = (blockIdx.x - gemm_blocks) * 256 + tid;
        if (i < n) {
            int c = g_cnt[i];
            int pc = (c + 7) & ~7;
            int base = g_row[i];
            for (int k = c; k < pc; k++) g_srcs[base + k] = n;
            g_cnt[i] = 0;
        }
        if (i < e) {
            int s = ei[i];
            int d = ei[e + i];
            g_srcs[g_row[d] + g_rank[i]] = s;
        }
        return;
    }

    // ---- GEMM layer-0 body (input projection prologue) ----
    int node0 = blockIdx.x * GROWS;

    for (int i = tid; i < HDIM * HDIM / 8; i += 256) {
        uint4 w = *reinterpret_cast<const uint4*>(&g_w16[0][i * 8]);
        int r = i >> 3;
        int c = (i * 8) & 63;
        *reinterpret_cast<uint4*>(&Wsm[r * ASTRIDE + c]) = w;
    }

#pragma unroll
    for (int it = 0; it < 8; it++) {
        int idx = tid + it * 256;
        int row = idx >> 4;
        int c4 = (idx & 15) * 4;
        int node = node0 + row;
        float4 v = make_float4(0.f, 0.f, 0.f, 0.f);
        if (node < n) {
            v = *reinterpret_cast<const float4*>(&bin[c4]);
#pragma unroll
            for (int k = 0; k < 5; k++) {
                float xv = __ldg(&x[node * 5 + k]);
                float4 w = *reinterpret_cast<const float4*>(&Win[k * HDIM + c4]);
                v.x = fmaf(xv, w.x, v.x);
                v.y = fmaf(xv, w.y, v.y);
                v.z = fmaf(xv, w.z, v.z);
                v.w = fmaf(xv, w.w, v.w);
            }
            v.x = fmaxf(v.x, 0.f); v.y = fmaxf(v.y, 0.f);
            v.z = fmaxf(v.z, 0.f); v.w = fmaxf(v.w, 0.f);
        }
        __half2 h0 = __floats2half2_rn(v.x, v.y);
        __half2 h1 = __floats2half2_rn(v.z, v.w);
        uint2 pk;
        pk.x = *reinterpret_cast<unsigned*>(&h0);
        pk.y = *reinterpret_cast<unsigned*>(&h1);
        *reinterpret_cast<uint2*>(&Asm[row * ASTRIDE + c4]) = pk;
    }
    __syncthreads();

    int warp = tid >> 5, lane = tid & 31;
    int wrow = warp * 16;

    unsigned a[4][4];
    {
        int r = lane & 15;
        int cb = (lane >> 4) << 3;
#pragma unroll
        for (int ks = 0; ks < 4; ks++) {
            unsigned addr = s2u(&Asm[(wrow + r) * ASTRIDE + ks * 16 + cb]);
            asm volatile("ldmatrix.sync.aligned.m8n8.x4.shared.b16 {%0,%1,%2,%3}, [%4];"
                         : "=r"(a[ks][0]), "=r"(a[ks][1]), "=r"(a[ks][2]), "=r"(a[ks][3])
                         : "r"(addr));
        }
    }

    float acc[8][4];
#pragma unroll
    for (int nt = 0; nt < 8; nt++)
#pragma unroll
        for (int q = 0; q < 4; q++) acc[nt][q] = 0.0f;

#pragma unroll
    for (int nt = 0; nt < 8; nt++) {
#pragma unroll
        for (int ks = 0; ks < 4; ks++) {
            unsigned b0, b1;
            int r = lane & 15;
            unsigned baddr = s2u(&Wsm[(ks * 16 + r) * ASTRIDE + nt * 8]);
            asm volatile("ldmatrix.sync.aligned.m8n8.x2.trans.shared.b16 {%0,%1}, [%2];"
                         : "=r"(b0), "=r"(b1) : "r"(baddr));
            asm volatile(
                "mma.sync.aligned.m16n8k16.row.col.f32.f16.f16.f32 "
                "{%0,%1,%2,%3}, {%4,%5,%6,%7}, {%8,%9}, {%0,%1,%2,%3};"
                : "+f"(acc[nt][0]), "+f"(acc[nt][1]), "+f"(acc[nt][2]), "+f"(acc[nt][3])
                : "r"(a[ks][0]), "r"(a[ks][1]), "r"(a[ks][2]), "r"(a[ks][3]),
                  "r"(b0), "r"(b1));
        }
    }

    int gr = lane >> 2;
    int qp = lane & 3;
    int node_a = node0 + wrow + gr;
    int node_b = node_a + 8;
    float dia = (node_a < n) ? g_dinv[node_a] : 0.f;
    float dib = (node_b < n) ? g_dinv[node_b] : 0.f;
#pragma unroll
    for (int nt = 0; nt < 8; nt++) {
        if (node_a < n)
            g_hs2[node_a * 32 + nt * 4 + qp] =
                __floats2half2_rn(acc[nt][0] * dia, acc[nt][1] * dia);
        if (node_b < n)
            g_hs2[node_b * 32 + nt * 4 + qp] =
                __floats2half2_rn(acc[nt][2] * dib, acc[nt][3] * dib);
    }
}

// ---------------------------------------------------------------------------
// Tensor-core GEMM (exact R10/R11 structure) for layers 1,2 (BN prologue).
__global__ void __launch_bounds__(256) k_gemm_mma(
    int n, int layer,
    const float* __restrict__ gamma, const float* __restrict__ beta) {
    __shared__ __half Asm[GROWS * ASTRIDE];
    __shared__ __half Wsm[HDIM * ASTRIDE];
    __shared__ float s_sc[HDIM], s_sf[HDIM];

    int tid = threadIdx.x;
    int node0 = blockIdx.x * GROWS;

    if (tid < HDIM) {
        float inv_n = 1.0f / (float)n;
        float mean = g_stats[layer - 1][tid] * inv_n;
        float var = g_stats[layer - 1][HDIM + tid] * inv_n - mean * mean;
        float inv = rsqrtf(var + BN_EPS);
        float sc = gamma[tid] * inv;
        s_sc[tid] = sc;
        s_sf[tid] = beta[tid] - mean * sc;
    }
    __syncthreads();

    for (int i = tid; i < HDIM * HDIM / 8; i += 256) {
        uint4 w = *reinterpret_cast<const uint4*>(&g_w16[layer][i * 8]);
        int r = i >> 3;
        int c = (i * 8) & 63;
        *reinterpret_cast<uint4*>(&Wsm[r * ASTRIDE + c]) = w;
    }

#pragma unroll
    for (int it = 0; it < 8; it++) {
        int idx = tid + it * 256;
        int row = idx >> 4;
        int c4 = (idx & 15) * 4;
        int node = node0 + row;
        float4 v = make_float4(0.f, 0.f, 0.f, 0.f);
        if (node < n) {
            v = *reinterpret_cast<const float4*>(&g_agg[node * HDIM + c4]);
            v.x = fmaf(v.x, s_sc[c4 + 0], s_sf[c4 + 0]);
            v.y = fmaf(v.y, s_sc[c4 + 1], s_sf[c4 + 1]);
            v.z = fmaf(v.z, s_sc[c4 + 2], s_sf[c4 + 2]);
            v.w = fmaf(v.w, s_sc[c4 + 3], s_sf[c4 + 3]);
            v.x = fmaxf(v.x, 0.f); v.y = fmaxf(v.y, 0.f);
            v.z = fmaxf(v.z, 0.f); v.w = fmaxf(v.w, 0.f);
        }
        __half2 h0 = __floats2half2_rn(v.x, v.y);
        __half2 h1 = __floats2half2_rn(v.z, v.w);
        uint2 pk;
        pk.x = *reinterpret_cast<unsigned*>(&h0);
        pk.y = *reinterpret_cast<unsigned*>(&h1);
        *reinterpret_cast<uint2*>(&Asm[row * ASTRIDE + c4]) = pk;
    }
    __syncthreads();

    int warp = tid >> 5, lane = tid & 31;
    int wrow = warp * 16;

    unsigned a[4][4];
    {
        int r = lane & 15;
        int cb = (lane >> 4) << 3;
#pragma unroll
        for (int ks = 0; ks < 4; ks++) {
            unsigned addr = s2u(&Asm[(wrow + r) * ASTRIDE + ks * 16 + cb]);
            asm volatile("ldmatrix.sync.aligned.m8n8.x4.shared.b16 {%0,%1,%2,%3}, [%4];"
                         : "=r"(a[ks][0]), "=r"(a[ks][1]), "=r"(a[ks][2]), "=r"(a[ks][3])
                         : "r"(addr));
        }
    }

    float acc[8][4];
#pragma unroll
    for (int nt = 0; nt < 8; nt++)
#pragma unroll
        for (int q = 0; q < 4; q++) acc[nt][q] = 0.0f;

#pragma unroll
    for (int nt = 0; nt < 8; nt++) {
#pragma unroll
        for (int ks = 0; ks < 4; ks++) {
            unsigned b0, b1;
            int r = lane & 15;
            unsigned baddr = s2u(&Wsm[(ks * 16 + r) * ASTRIDE + nt * 8]);
            asm volatile("ldmatrix.sync.aligned.m8n8.x2.trans.shared.b16 {%0,%1}, [%2];"
                         : "=r"(b0), "=r"(b1) : "r"(baddr));
            asm volatile(
                "mma.sync.aligned.m16n8k16.row.col.f32.f16.f16.f32 "
                "{%0,%1,%2,%3}, {%4,%5,%6,%7}, {%8,%9}, {%0,%1,%2,%3};"
                : "+f"(acc[nt][0]), "+f"(acc[nt][1]), "+f"(acc[nt][2]), "+f"(acc[nt][3])
                : "r"(a[ks][0]), "r"(a[ks][1]), "r"(a[ks][2]), "r"(a[ks][3]),
                  "r"(b0), "r"(b1));
        }
    }

    int gr = lane >> 2;
    int qp = lane & 3;
    int node_a = node0 + wrow + gr;
    int node_b = node_a + 8;
    float dia = (node_a < n) ? g_dinv[node_a] : 0.f;
    float dib = (node_b < n) ? g_dinv[node_b] : 0.f;
#pragma unroll
    for (int nt = 0; nt < 8; nt++) {
        if (node_a < n)
            g_hs2[node_a * 32 + nt * 4 + qp] =
                __floats2half2_rn(acc[nt][0] * dia, acc[nt][1] * dia);
        if (node_b < n)
            g_hs2[node_b * 32 + nt * 4 + qp] =
                __floats2half2_rn(acc[nt][2] * dib, acc[nt][3] * dib);
    }
}

// ---------------------------------------------------------------------------
// pull-based aggregation + BN stats. Padded buckets (sentinel n, zero row).
// NODES_PER_WARP=4 (measured-best granularity, R13).
#define AGG_WARPS 8
#define NODES_PER_WARP 4
__global__ void k_aggregate(int n, int layer) {
    __shared__ float s_sum[HDIM], s_sq[HDIM];
    int tid = threadIdx.x, lane = tid & 31, warp = tid >> 5;
    if (tid < HDIM) { s_sum[tid] = 0.f; s_sq[tid] = 0.f; }
    __syncthreads();

    float ls0 = 0.f, lq0 = 0.f, ls1 = 0.f, lq1 = 0.f;
    int node0 = (blockIdx.x * AGG_WARPS + warp) * NODES_PER_WARP;

    for (int i = 0; i < NODES_PER_WARP; i++) {
        int node = node0 + i;
        if (node >= n) break;
        int beg = g_row[node], end = g_row[node + 1];
        float a0 = 0.f, a1 = 0.f;
        for (int j = beg; j < end; j += 8) {
            int4 sa = *reinterpret_cast<const int4*>(&g_srcs[j]);
            int4 sb = *reinterpret_cast<const int4*>(&g_srcs[j + 4]);
            float2 f[8];
            f[0] = __half22float2(g_hs2[sa.x * 32 + lane]);
            f[1] = __half22float2(g_hs2[sa.y * 32 + lane]);
            f[2] = __half22float2(g_hs2[sa.z * 32 + lane]);
            f[3] = __half22float2(g_hs2[sa.w * 32 + lane]);
            f[4] = __half22float2(g_hs2[sb.x * 32 + lane]);
            f[5] = __half22float2(g_hs2[sb.y * 32 + lane]);
            f[6] = __half22float2(g_hs2[sb.z * 32 + lane]);
            f[7] = __half22float2(g_hs2[sb.w * 32 + lane]);
#pragma unroll
            for (int u = 0; u < 8; u++) { a0 += f[u].x; a1 += f[u].y; }
        }
        float2 self = __half22float2(g_hs2[node * 32 + lane]);
        float di = g_dinv[node];
        a0 = (a0 + self.x) * di;
        a1 = (a1 + self.y) * di;
        float2 o; o.x = a0; o.y = a1;
        *reinterpret_cast<float2*>(&g_agg[node * HDIM + 2 * lane]) = o;
        ls0 += a0; lq0 = fmaf(a0, a0, lq0);
        ls1 += a1; lq1 = fmaf(a1, a1, lq1);
    }

    atomicAdd(&s_sum[2 * lane], ls0);
    atomicAdd(&s_sq[2 * lane], lq0);
    atomicAdd(&s_sum[2 * lane + 1], ls1);
    atomicAdd(&s_sq[2 * lane + 1], lq1);
    __syncthreads();
    if (tid < HDIM) {
        atomicAdd(&g_stats[layer][tid], s_sum[tid]);
        atomicAdd(&g_stats[layer][HDIM + tid], s_sq[tid]);
    }
}

// ---------------------------------------------------------------------------
// classifier with in-block final BN+ReLU: out = relu(bn(agg) @ W1 + b1) @ W2 + b2
__global__ void k_classifier(const float* __restrict__ W1,
                             const float* __restrict__ b1,
                             const float* __restrict__ W2,
                             const float* __restrict__ b2,
                             const float* __restrict__ gamma,
                             const float* __restrict__ beta,
                             float* __restrict__ out, int n) {
    __shared__ float W1sm[HDIM * HC];
    __shared__ float s_sc[HDIM], s_sf[HDIM];
    int tid = threadIdx.x;
    if (tid < HDIM) {
        float inv_n = 1.0f / (float)n;
        float mean = g_stats[NLAYERS - 1][tid] * inv_n;
        float var = g_stats[NLAYERS - 1][HDIM + tid] * inv_n - mean * mean;
        float inv = rsqrtf(var + BN_EPS);
        float sc = gamma[tid] * inv;
        s_sc[tid] = sc;
        s_sf[tid] = beta[tid] - mean * sc;
    }
#pragma unroll
    for (int i = tid; i < HDIM * HC; i += 256) W1sm[i] = W1[i];
    __syncthreads();

    int lane = tid & 31;
    int warp = tid >> 5;
    float b1v = b1[lane];
    float w2v = W2[lane];
    float b2v = b2[0];
    float sc0 = s_sc[lane],      sf0 = s_sf[lane];
    float sc1 = s_sc[lane + 32], sf1 = s_sf[lane + 32];
    int base = blockIdx.x * 64 + warp * 8;

    for (int i = 0; i < 8; i++) {
        int node = base + i;
        if (node >= n) break;
        float h0 = fmaxf(fmaf(g_agg[node * HDIM + lane],      sc0, sf0), 0.f);
        float h1 = fmaxf(fmaf(g_agg[node * HDIM + 32 + lane], sc1, sf1), 0.f);
        float acc = b1v;
#pragma unroll
        for (int k = 0; k < 32; k++)
            acc = fmaf(__shfl_sync(0xFFFFFFFFu, h0, k), W1sm[k * HC + lane], acc);
#pragma unroll
        for (int k = 0; k < 32; k++)
            acc = fmaf(__shfl_sync(0xFFFFFFFFu, h1, k), W1sm[(k + 32) * HC + lane], acc);
        float r = fmaxf(acc, 0.0f) * w2v;
#pragma unroll
        for (int off = 16; off > 0; off >>= 1)
            r += __shfl_xor_sync(0xFFFFFFFFu, r, off);
        if (lane == 0) out[node] = r + b2v;
    }
}

// ---------------------------------------------------------------------------
extern "C" void kernel_launch(void* const* d_in, const int* in_sizes, int n_in,
                              void* d_out, int out_size) {
    const float* x        = (const float*)d_in[0];
    const int*   ei       = (const int*)d_in[1];
    const float* W_in     = (const float*)d_in[2];
    const float* b_in     = (const float*)d_in[3];
    const float* conv_W   = (const float*)d_in[4];
    // d_in[5] = conv_b : cancels exactly inside BatchNorm -> unused
    const float* bn_gamma = (const float*)d_in[6];
    const float* bn_beta  = (const float*)d_in[7];
    const float* W1       = (const float*)d_in[8];
    const float* b1       = (const float*)d_in[9];
    const float* W2       = (const float*)d_in[10];
    const float* b2       = (const float*)d_in[11];
    float* out = (float*)d_out;

    int n = in_sizes[0] / 5;
    int e = in_sizes[1] / 2;
    int nb = (n + SCAN_BLK - 1) / SCAN_BLK;

    int gemm_blocks = (n + GROWS - 1) / GROWS;
    int bucket_blocks = (e + 255) / 256;
    int agg_blocks = (n + AGG_WARPS * NODES_PER_WARP - 1) / (AGG_WARPS * NODES_PER_WARP);

    k_count_deg<<<bucket_blocks, 256>>>(ei + e, e, n, conv_W);
    k_scan_fused<<<nb, 256>>>(n);

    // fused: GEMM layer 0 (blocks [0,gemm_blocks)) + bucket (rest)
    k_bucket_gemm0<<<gemm_blocks + bucket_blocks, 256>>>(
        ei, e, n, gemm_blocks, x, W_in, b_in);
    k_aggregate<<<agg_blocks, 256>>>(n, 0);

    for (int l = 1; l < NLAYERS; l++) {
        k_gemm_mma<<<gemm_blocks, 256>>>(
            n, l, bn_gamma + (l - 1) * HDIM, bn_beta + (l - 1) * HDIM);
        k_aggregate<<<agg_blocks, 256>>>(n, l);
    }

    k_classifier<<<(n + 63) / 64, 256>>>(
        W1, b1, W2, b2,
        bn_gamma + (NLAYERS - 1) * HDIM, bn_beta + (NLAYERS - 1) * HDIM, out, n);
}

// round 17
// speedup vs baseline: 1.0514x; 1.0038x over previous
#include <cuda_runtime.h>
#include <cuda_fp16.h>

#define NMAX 100000
#define EMAX 1600000
#define EPAD (EMAX + 8 * NMAX + 8)
#define HDIM 64
#define HC 32
#define NLAYERS 3
#define BN_EPS 1e-5f
#define SCAN_BLK 1024
#define SCAN_MAXB 128

// ---- scratch (device globals; no allocation allowed) ----
__device__ __half2 g_hs2[(NMAX + 1) * 32]; // (h @ W) * dinv[row]; row n = zero sentinel
__device__ float g_agg[NMAX * HDIM];       // pre-BN aggregated features (fp32)
__device__ int   g_cnt [NMAX];             // in-degree counts (left at 0 on exit)
__device__ float g_dinv[NMAX];             // (deg+1)^-1/2
__device__ int   g_row [NMAX + 1];         // padded CSR row pointers (by dst)
__device__ int   g_rank[EMAX];             // per-edge rank within its dst bucket
__device__ int   g_srcs[EPAD];             // src ids sorted by dst, padded to 8 (+8 guard)
__device__ volatile int g_part[SCAN_MAXB]; // lookback partials (total+1)
__device__ float g_stats[NLAYERS][2 * HDIM]; // per-layer channel sum, sumsq
__device__ __half g_w16[NLAYERS][HDIM * HDIM]; // conv weights pre-converted fp16

static __device__ __forceinline__ unsigned s2u(const void* p) {
    return (unsigned)__cvta_generic_to_shared(p);
}

// ---------------------------------------------------------------------------
// count in-degrees, record per-edge rank; block 0 zeroes partials + BN stats;
// blocks 1..NLAYERS convert conv_W[layer] to fp16; block NLAYERS+1 zeroes the
// sentinel hs2 row (row n).
__global__ void k_count_deg(const int* __restrict__ dst, int e, int n,
                            const float* __restrict__ conv_W) {
    int i = blockIdx.x * blockDim.x + threadIdx.x;
    if (blockIdx.x == 0) {
        if (threadIdx.x < SCAN_MAXB) *(int*)&g_part[threadIdx.x] = 0;
        for (int j = threadIdx.x; j < NLAYERS * 2 * HDIM; j += 256)
            (&g_stats[0][0])[j] = 0.0f;
    } else if (blockIdx.x <= NLAYERS) {
        int l = blockIdx.x - 1;
        const float* W = conv_W + l * HDIM * HDIM;
        for (int j = threadIdx.x; j < HDIM * HDIM / 4; j += 256) {
            float4 w = *reinterpret_cast<const float4*>(&W[j * 4]);
            __half2 h0 = __floats2half2_rn(w.x, w.y);
            __half2 h1 = __floats2half2_rn(w.z, w.w);
            uint2 pk;
            pk.x = *reinterpret_cast<unsigned*>(&h0);
            pk.y = *reinterpret_cast<unsigned*>(&h1);
            *reinterpret_cast<uint2*>(&g_w16[l][j * 4]) = pk;
        }
    } else if (blockIdx.x == NLAYERS + 1) {
        if (threadIdx.x < 32)
            g_hs2[n * 32 + threadIdx.x] = __floats2half2_rn(0.f, 0.f);
    }
    if (i < e) g_rank[i] = atomicAdd(&g_cnt[dst[i]], 1);
}

// fused scan: dinv from real counts + exclusive prefix of PADDED counts
__global__ void k_scan_fused(int n) {
    __shared__ int sh[256];
    int tid = threadIdx.x, b = blockIdx.x;
    int base = b * SCAN_BLK + tid * 4;

    int v[4]; int mine = 0;
    if (base + 4 <= n) {
        int4 c = *reinterpret_cast<const int4*>(&g_cnt[base]);
        g_dinv[base + 0] = rsqrtf((float)c.x + 1.0f);
        g_dinv[base + 1] = rsqrtf((float)c.y + 1.0f);
        g_dinv[base + 2] = rsqrtf((float)c.z + 1.0f);
        g_dinv[base + 3] = rsqrtf((float)c.w + 1.0f);
        v[0] = (c.x + 7) & ~7; v[1] = (c.y + 7) & ~7;
        v[2] = (c.z + 7) & ~7; v[3] = (c.w + 7) & ~7;
        mine = v[0] + v[1] + v[2] + v[3];
    } else {
#pragma unroll
        for (int k = 0; k < 4; k++) {
            v[k] = 0;
            if (base + k < n) {
                int c = g_cnt[base + k];
                g_dinv[base + k] = rsqrtf((float)c + 1.0f);
                v[k] = (c + 7) & ~7;
                mine += v[k];
            }
        }
    }

    sh[tid] = mine;
    __syncthreads();
    for (int o = 1; o < 256; o <<= 1) {
        int t = (tid >= o) ? sh[tid - o] : 0;
        __syncthreads();
        sh[tid] += t;
        __syncthreads();
    }
    int excl = sh[tid] - mine;
    int total = sh[255];

    if (tid == 0) atomicExch((int*)&g_part[b], total + 1);
    int pref = 0;
    for (int i = tid; i < b; i += 256) {
        int p;
        while ((p = g_part[i]) == 0) {}
        pref += p - 1;
    }
    __syncthreads();
    sh[tid] = pref;
    __syncthreads();
    for (int o = 128; o > 0; o >>= 1) {
        if (tid < o) sh[tid] += sh[tid + o];
        __syncthreads();
    }
    int off = sh[0] + excl;

#pragma unroll
    for (int k = 0; k < 4; k++) {
        int idx = base + k;
        if (idx < n) {
            g_row[idx] = off;
            off += v[k];
            if (idx == n - 1) g_row[n] = off;
        }
    }
}

// bucket placement + pad fill with sentinel n; re-zero g_cnt
__global__ void k_bucket(const int* __restrict__ ei, int e, int n) {
    int i = blockIdx.x * blockDim.x + threadIdx.x;
    if (i < n) {
        int c = g_cnt[i];
        int pc = (c + 7) & ~7;
        int base = g_row[i];
        for (int k = c; k < pc; k++) g_srcs[base + k] = n;
        g_cnt[i] = 0;
    }
    if (i >= e) return;
    int s = ei[i];
    int d = ei[e + i];
    g_srcs[g_row[d] + g_rank[i]] = s;
}

// ---------------------------------------------------------------------------
// Tensor-core GEMM (exact R10/R13 structure): 128 nodes x 64 cols, 8 warps.
#define GROWS 128
#define ASTRIDE 72   // halves; 144B rows: 16B aligned, ldmatrix conflict-free
__global__ void __launch_bounds__(256) k_gemm_mma(
    int n, int layer,
    const float* __restrict__ x, const float* __restrict__ Win,
    const float* __restrict__ bin,
    const float* __restrict__ gamma, const float* __restrict__ beta) {
    __shared__ __half Asm[GROWS * ASTRIDE];
    __shared__ __half Wsm[HDIM * ASTRIDE];
    __shared__ float s_sc[HDIM], s_sf[HDIM];

    int tid = threadIdx.x;
    int node0 = blockIdx.x * GROWS;

    if (layer > 0) {
        if (tid < HDIM) {
            float inv_n = 1.0f / (float)n;
            float mean = g_stats[layer - 1][tid] * inv_n;
            float var = g_stats[layer - 1][HDIM + tid] * inv_n - mean * mean;
            float inv = rsqrtf(var + BN_EPS);
            float sc = gamma[tid] * inv;
            s_sc[tid] = sc;
            s_sf[tid] = beta[tid] - mean * sc;
        }
        __syncthreads();
    }

    // W (64x64 fp16, pre-converted) -> smem, uint4 = 8 halves
    for (int i = tid; i < HDIM * HDIM / 8; i += 256) {
        uint4 w = *reinterpret_cast<const uint4*>(&g_w16[layer][i * 8]);
        int r = i >> 3;
        int c = (i * 8) & 63;
        *reinterpret_cast<uint4*>(&Wsm[r * ASTRIDE + c]) = w;
    }

    // A tile (128 x 64) -> fp16 smem, fused BN/relu or input-proj
#pragma unroll
    for (int it = 0; it < 8; it++) {
        int idx = tid + it * 256;
        int row = idx >> 4;
        int c4 = (idx & 15) * 4;
        int node = node0 + row;
        float4 v = make_float4(0.f, 0.f, 0.f, 0.f);
        if (node < n) {
            if (layer > 0) {
                v = *reinterpret_cast<const float4*>(&g_agg[node * HDIM + c4]);
                v.x = fmaf(v.x, s_sc[c4 + 0], s_sf[c4 + 0]);
                v.y = fmaf(v.y, s_sc[c4 + 1], s_sf[c4 + 1]);
                v.z = fmaf(v.z, s_sc[c4 + 2], s_sf[c4 + 2]);
                v.w = fmaf(v.w, s_sc[c4 + 3], s_sf[c4 + 3]);
            } else {
                v = *reinterpret_cast<const float4*>(&bin[c4]);
#pragma unroll
                for (int k = 0; k < 5; k++) {
                    float xv = __ldg(&x[node * 5 + k]);
                    float4 w = *reinterpret_cast<const float4*>(&Win[k * HDIM + c4]);
                    v.x = fmaf(xv, w.x, v.x);
                    v.y = fmaf(xv, w.y, v.y);
                    v.z = fmaf(xv, w.z, v.z);
                    v.w = fmaf(xv, w.w, v.w);
                }
            }
            v.x = fmaxf(v.x, 0.f); v.y = fmaxf(v.y, 0.f);
            v.z = fmaxf(v.z, 0.f); v.w = fmaxf(v.w, 0.f);
        }
        __half2 h0 = __floats2half2_rn(v.x, v.y);
        __half2 h1 = __floats2half2_rn(v.z, v.w);
        uint2 pk;
        pk.x = *reinterpret_cast<unsigned*>(&h0);
        pk.y = *reinterpret_cast<unsigned*>(&h1);
        *reinterpret_cast<uint2*>(&Asm[row * ASTRIDE + c4]) = pk;
    }
    __syncthreads();

    int warp = tid >> 5, lane = tid & 31;
    int wrow = warp * 16;

    // A fragments for all 4 k-steps (m16k16 each)
    unsigned a[4][4];
    {
        int r = lane & 15;
        int cb = (lane >> 4) << 3;
#pragma unroll
        for (int ks = 0; ks < 4; ks++) {
            unsigned addr = s2u(&Asm[(wrow + r) * ASTRIDE + ks * 16 + cb]);
            asm volatile("ldmatrix.sync.aligned.m8n8.x4.shared.b16 {%0,%1,%2,%3}, [%4];"
                         : "=r"(a[ks][0]), "=r"(a[ks][1]), "=r"(a[ks][2]), "=r"(a[ks][3])
                         : "r"(addr));
        }
    }

    float acc[8][4];
#pragma unroll
    for (int nt = 0; nt < 8; nt++)
#pragma unroll
        for (int q = 0; q < 4; q++) acc[nt][q] = 0.0f;

#pragma unroll
    for (int nt = 0; nt < 8; nt++) {
#pragma unroll
        for (int ks = 0; ks < 4; ks++) {
            unsigned b0, b1;
            int r = lane & 15;
            unsigned baddr = s2u(&Wsm[(ks * 16 + r) * ASTRIDE + nt * 8]);
            asm volatile("ldmatrix.sync.aligned.m8n8.x2.trans.shared.b16 {%0,%1}, [%2];"
                         : "=r"(b0), "=r"(b1) : "r"(baddr));
            asm volatile(
                "mma.sync.aligned.m16n8k16.row.col.f32.f16.f16.f32 "
                "{%0,%1,%2,%3}, {%4,%5,%6,%7}, {%8,%9}, {%0,%1,%2,%3};"
                : "+f"(acc[nt][0]), "+f"(acc[nt][1]), "+f"(acc[nt][2]), "+f"(acc[nt][3])
                : "r"(a[ks][0]), "r"(a[ks][1]), "r"(a[ks][2]), "r"(a[ks][3]),
                  "r"(b0), "r"(b1));
        }
    }

    // epilogue: scale by dinv, pack fp16, store
    int gr = lane >> 2;
    int qp = lane & 3;
    int node_a = node0 + wrow + gr;
    int node_b = node_a + 8;
    float dia = (node_a < n) ? g_dinv[node_a] : 0.f;
    float dib = (node_b < n) ? g_dinv[node_b] : 0.f;
#pragma unroll
    for (int nt = 0; nt < 8; nt++) {
        if (node_a < n)
            g_hs2[node_a * 32 + nt * 4 + qp] =
                __floats2half2_rn(acc[nt][0] * dia, acc[nt][1] * dia);
        if (node_b < n)
            g_hs2[node_b * 32 + nt * 4 + qp] =
                __floats2half2_rn(acc[nt][2] * dib, acc[nt][3] * dib);
    }
}

// ---------------------------------------------------------------------------
// pull-based aggregation + BN stats. Padded buckets (sentinel n, zero row).
// SOFTWARE-PIPELINED: next iteration's src ids prefetched before consuming
// this iteration's gathers (breaks the id-load -> gather dependent chain).
#define AGG_WARPS 8
#define NODES_PER_WARP 4
__global__ void k_aggregate(int n, int layer) {
    __shared__ float s_sum[HDIM], s_sq[HDIM];
    int tid = threadIdx.x, lane = tid & 31, warp = tid >> 5;
    if (tid < HDIM) { s_sum[tid] = 0.f; s_sq[tid] = 0.f; }
    __syncthreads();

    float ls0 = 0.f, lq0 = 0.f, ls1 = 0.f, lq1 = 0.f;
    int node0 = (blockIdx.x * AGG_WARPS + warp) * NODES_PER_WARP;

    for (int i = 0; i < NODES_PER_WARP; i++) {
        int node = node0 + i;
        if (node >= n) break;
        int beg = g_row[node], end = g_row[node + 1];
        float a0 = 0.f, a1 = 0.f;
        if (beg < end) {
            int4 sa = *reinterpret_cast<const int4*>(&g_srcs[beg]);
            int4 sb = *reinterpret_cast<const int4*>(&g_srcs[beg + 4]);
            for (int j = beg; j < end; j += 8) {
                // prefetch next ids (guard slots make this always in-bounds;
                // values unused on final iteration)
                int4 na = *reinterpret_cast<const int4*>(&g_srcs[j + 8]);
                int4 nb = *reinterpret_cast<const int4*>(&g_srcs[j + 12]);
                float2 f[8];
                f[0] = __half22float2(g_hs2[sa.x * 32 + lane]);
                f[1] = __half22float2(g_hs2[sa.y * 32 + lane]);
                f[2] = __half22float2(g_hs2[sa.z * 32 + lane]);
                f[3] = __half22float2(g_hs2[sa.w * 32 + lane]);
                f[4] = __half22float2(g_hs2[sb.x * 32 + lane]);
                f[5] = __half22float2(g_hs2[sb.y * 32 + lane]);
                f[6] = __half22float2(g_hs2[sb.z * 32 + lane]);
                f[7] = __half22float2(g_hs2[sb.w * 32 + lane]);
#pragma unroll
                for (int u = 0; u < 8; u++) { a0 += f[u].x; a1 += f[u].y; }
                sa = na; sb = nb;
            }
        }
        float2 self = __half22float2(g_hs2[node * 32 + lane]);
        float di = g_dinv[node];
        a0 = (a0 + self.x) * di;
        a1 = (a1 + self.y) * di;
        float2 o; o.x = a0; o.y = a1;
        *reinterpret_cast<float2*>(&g_agg[node * HDIM + 2 * lane]) = o;
        ls0 += a0; lq0 = fmaf(a0, a0, lq0);
        ls1 += a1; lq1 = fmaf(a1, a1, lq1);
    }

    atomicAdd(&s_sum[2 * lane], ls0);
    atomicAdd(&s_sq[2 * lane], lq0);
    atomicAdd(&s_sum[2 * lane + 1], ls1);
    atomicAdd(&s_sq[2 * lane + 1], lq1);
    __syncthreads();
    if (tid < HDIM) {
        atomicAdd(&g_stats[layer][tid], s_sum[tid]);
        atomicAdd(&g_stats[layer][HDIM + tid], s_sq[tid]);
    }
}

// ---------------------------------------------------------------------------
// classifier with in-block final BN+ReLU: out = relu(bn(agg) @ W1 + b1) @ W2 + b2
__global__ void k_classifier(const float* __restrict__ W1,
                             const float* __restrict__ b1,
                             const float* __restrict__ W2,
                             const float* __restrict__ b2,
                             const float* __restrict__ gamma,
                             const float* __restrict__ beta,
                             float* __restrict__ out, int n) {
    __shared__ float W1sm[HDIM * HC];
    __shared__ float s_sc[HDIM], s_sf[HDIM];
    int tid = threadIdx.x;
    if (tid < HDIM) {
        float inv_n = 1.0f / (float)n;
        float mean = g_stats[NLAYERS - 1][tid] * inv_n;
        float var = g_stats[NLAYERS - 1][HDIM + tid] * inv_n - mean * mean;
        float inv = rsqrtf(var + BN_EPS);
        float sc = gamma[tid] * inv;
        s_sc[tid] = sc;
        s_sf[tid] = beta[tid] - mean * sc;
    }
#pragma unroll
    for (int i = tid; i < HDIM * HC; i += 256) W1sm[i] = W1[i];
    __syncthreads();

    int lane = tid & 31;
    int warp = tid >> 5;
    float b1v = b1[lane];
    float w2v = W2[lane];
    float b2v = b2[0];
    float sc0 = s_sc[lane],      sf0 = s_sf[lane];
    float sc1 = s_sc[lane + 32], sf1 = s_sf[lane + 32];
    int base = blockIdx.x * 64 + warp * 8;

    for (int i = 0; i < 8; i++) {
        int node = base + i;
        if (node >= n) break;
        float h0 = fmaxf(fmaf(g_agg[node * HDIM + lane],      sc0, sf0), 0.f);
        float h1 = fmaxf(fmaf(g_agg[node * HDIM + 32 + lane], sc1, sf1), 0.f);
        float acc = b1v;
#pragma unroll
        for (int k = 0; k < 32; k++)
            acc = fmaf(__shfl_sync(0xFFFFFFFFu, h0, k), W1sm[k * HC + lane], acc);
#pragma unroll
        for (int k = 0; k < 32; k++)
            acc = fmaf(__shfl_sync(0xFFFFFFFFu, h1, k), W1sm[(k + 32) * HC + lane], acc);
        float r = fmaxf(acc, 0.0f) * w2v;
#pragma unroll
        for (int off = 16; off > 0; off >>= 1)
            r += __shfl_xor_sync(0xFFFFFFFFu, r, off);
        if (lane == 0) out[node] = r + b2v;
    }
}

// ---------------------------------------------------------------------------
extern "C" void kernel_launch(void* const* d_in, const int* in_sizes, int n_in,
                              void* d_out, int out_size) {
    const float* x        = (const float*)d_in[0];
    const int*   ei       = (const int*)d_in[1];
    const float* W_in     = (const float*)d_in[2];
    const float* b_in     = (const float*)d_in[3];
    const float* conv_W   = (const float*)d_in[4];
    // d_in[5] = conv_b : cancels exactly inside BatchNorm -> unused
    const float* bn_gamma = (const float*)d_in[6];
    const float* bn_beta  = (const float*)d_in[7];
    const float* W1       = (const float*)d_in[8];
    const float* b1       = (const float*)d_in[9];
    const float* W2       = (const float*)d_in[10];
    const float* b2       = (const float*)d_in[11];
    float* out = (float*)d_out;

    int n = in_sizes[0] / 5;
    int e = in_sizes[1] / 2;
    int nb = (n + SCAN_BLK - 1) / SCAN_BLK;

    int gemm_blocks = (n + GROWS - 1) / GROWS;
    int agg_blocks = (n + AGG_WARPS * NODES_PER_WARP - 1) / (AGG_WARPS * NODES_PER_WARP);

    k_count_deg<<<(e + 255) / 256, 256>>>(ei + e, e, n, conv_W);
    k_scan_fused<<<nb, 256>>>(n);
    k_bucket<<<(e + 255) / 256, 256>>>(ei, e, n);

    for (int l = 0; l < NLAYERS; l++) {
        k_gemm_mma<<<gemm_blocks, 256>>>(
            n, l, x, W_in, b_in,
            l > 0 ? bn_gamma + (l - 1) * HDIM : nullptr,
            l > 0 ? bn_beta + (l - 1) * HDIM : nullptr);
        k_aggregate<<<agg_blocks, 256>>>(n, l);
    }

    k_classifier<<<(n + 63) / 64, 256>>>(
        W1, b1, W2, b2,
        bn_gamma + (NLAYERS - 1) * HDIM, bn_beta + (NLAYERS - 1) * HDIM, out, n);
}